// round 15
// baseline (speedup 1.0000x reference)
#include <cuda_runtime.h>
#include <cuda_fp16.h>
#include <mma.h>
#include <math.h>
#include <stdint.h>

using namespace nvcuda;

#define B_ 4
#define N_ 2048
#define IN_F 512
#define OUT_F 512
#define INTERNAL 256
#define REL_DIM 10
#define NUM_REL 6
#define ALPHA_ 0.2f
#define NEG_INF_ -9000000000000000.0f
#define EPS_LN_ 1e-5f

#define LAMBDA_INIT_ 0.35550906759096927f
#define ONE_MINUS_LAMBDA_ 0.64449093240903073f

// ---------------------------------------------------------------------------
// Device scratch
// ---------------------------------------------------------------------------
__device__ __align__(128) float g_hprime[(size_t)B_ * N_ * OUT_F];
__device__ __align__(128) float g_att_fallback[(size_t)B_ * N_ * N_];
__device__ __align__(128) __half g_h_h16[(size_t)B_ * N_ * IN_F];
__device__ __align__(128) __half g_W_h16[(size_t)IN_F * OUT_F];
__device__ __align__(128) __half g_Wh_h16[(size_t)B_ * N_ * OUT_F];
__device__ __align__(128) __half g_att_h16[(size_t)B_ * N_ * N_];
__device__ float g_vlp[IN_F];
__device__ float g_vrp[IN_F];
__device__ float g_vln[IN_F];
__device__ float g_vrn[IN_F];
__device__ float g_lpos[B_ * N_];
__device__ float g_rpos[B_ * N_];
__device__ float g_lneg[B_ * N_];
__device__ float g_rneg[B_ * N_];
__device__ float g_relp[NUM_REL];
__device__ float g_reln[NUM_REL];
__device__ float g_lam;

// ---------------------------------------------------------------------------
// Host-side stream/event resources (created at load, before harness baseline)
// ---------------------------------------------------------------------------
struct GraphRes {
    cudaStream_t s2 = nullptr, s3 = nullptr;
    cudaEvent_t ev_fork = nullptr, ev_done = nullptr;
    cudaEvent_t ev_g1[B_] = {}, ev_att[B_] = {};
    GraphRes() {
        cudaStreamCreateWithFlags(&s2, cudaStreamNonBlocking);
        cudaStreamCreateWithFlags(&s3, cudaStreamNonBlocking);
        cudaEventCreateWithFlags(&ev_fork, cudaEventDisableTiming);
        cudaEventCreateWithFlags(&ev_done, cudaEventDisableTiming);
        for (int b = 0; b < B_; b++) {
            cudaEventCreateWithFlags(&ev_g1[b], cudaEventDisableTiming);
            cudaEventCreateWithFlags(&ev_att[b], cudaEventDisableTiming);
        }
    }
};
static GraphRes g_res;

// ---------------------------------------------------------------------------
// cp.async helpers
// ---------------------------------------------------------------------------
__device__ __forceinline__ uint32_t smem_u32(const void* p) {
    uint32_t a;
    asm("{ .reg .u64 t; cvta.to.shared.u64 t, %1; cvt.u32.u64 %0, t; }" : "=r"(a) : "l"(p));
    return a;
}
__device__ __forceinline__ void cp_async16(uint32_t s, const void* g) {
    asm volatile("cp.async.cg.shared.global [%0], [%1], 16;" :: "r"(s), "l"(g));
}
#define CP_COMMIT() asm volatile("cp.async.commit_group;" ::: "memory")
#define CP_WAIT(n) asm volatile("cp.async.wait_group %0;" :: "n"(n) : "memory")

// ---------------------------------------------------------------------------
// Merged prep: W fold + fp16 conversion (blocks 0..IN_F-1), lambda/LUT (block IN_F)
// ---------------------------------------------------------------------------
__global__ void prep_all_kernel(const float* __restrict__ W,
                                const float* __restrict__ alp, const float* __restrict__ arp,
                                const float* __restrict__ aln, const float* __restrict__ arn,
                                const float* __restrict__ ll1, const float* __restrict__ lr1,
                                const float* __restrict__ ll2, const float* __restrict__ lr2,
                                const float* __restrict__ rel_table,
                                const float* __restrict__ a_rel_pos,
                                const float* __restrict__ a_rel_neg) {
    int t = threadIdx.x;
    if (blockIdx.x == IN_F) {
        __shared__ float s1[256];
        __shared__ float s2[256];
        s1[t] = ll1[t] * lr1[t];
        s2[t] = ll2[t] * lr2[t];
        __syncthreads();
        for (int s = 128; s > 0; s >>= 1) {
            if (t < s) { s1[t] += s1[t + s]; s2[t] += s2[t + s]; }
            __syncthreads();
        }
        if (t == 0) g_lam = expf(s1[0]) - expf(s2[0]) + LAMBDA_INIT_;
        if (t < NUM_REL) {
            float sp = 0.f, sn = 0.f;
            #pragma unroll
            for (int d = 0; d < REL_DIM; d++) {
                float r = rel_table[t * REL_DIM + d];
                sp += r * a_rel_pos[d];
                sn += r * a_rel_neg[d];
            }
            g_relp[t] = sp;
            g_reln[t] = sn;
        }
        return;
    }
    int i = blockIdx.x;
    const float* wrow = W + (size_t)i * OUT_F;
    float wp = wrow[t];
    float wn = wrow[INTERNAL + t];

    __half* wr = g_W_h16 + (size_t)i * OUT_F;
    wr[t] = __float2half_rn(wp);
    wr[INTERNAL + t] = __float2half_rn(wn);

    __shared__ float s[4][256];
    s[0][t] = wp * alp[t];
    s[1][t] = wp * arp[t];
    s[2][t] = wn * aln[t];
    s[3][t] = wn * arn[t];
    __syncthreads();
    for (int st = 128; st > 0; st >>= 1) {
        if (t < st) {
            s[0][t] += s[0][t + st];
            s[1][t] += s[1][t + st];
            s[2][t] += s[2][t + st];
            s[3][t] += s[3][t + st];
        }
        __syncthreads();
    }
    if (t == 0) {
        g_vlp[i] = s[0][0];
        g_vrp[i] = s[1][0];
        g_vln[i] = s[2][0];
        g_vrn[i] = s[3][0];
    }
}

// ---------------------------------------------------------------------------
// Fused: h -> fp16 + exact per-row scores via GEMV against folded vectors.
// ---------------------------------------------------------------------------
__global__ void hconv_scores_kernel(const float* __restrict__ h) {
    int row = blockIdx.x;
    int t = threadIdx.x;
    const float* hr = h + (size_t)row * IN_F;
    float x0 = hr[t];
    float x1 = hr[t + 256];

    __half* hh = g_h_h16 + (size_t)row * IN_F;
    hh[t] = __float2half_rn(x0);
    hh[t + 256] = __float2half_rn(x1);

    __shared__ float s[4][256];
    s[0][t] = x0 * g_vlp[t] + x1 * g_vlp[t + 256];
    s[1][t] = x0 * g_vrp[t] + x1 * g_vrp[t + 256];
    s[2][t] = x0 * g_vln[t] + x1 * g_vln[t + 256];
    s[3][t] = x0 * g_vrn[t] + x1 * g_vrn[t + 256];
    __syncthreads();
    for (int st = 128; st > 0; st >>= 1) {
        if (t < st) {
            s[0][t] += s[0][t + st];
            s[1][t] += s[1][t + st];
            s[2][t] += s[2][t + st];
            s[3][t] += s[3][t + st];
        }
        __syncthreads();
    }
    if (t == 0) {
        g_lpos[row] = s[0][0];
        g_rpos[row] = s[1][0];
        g_lneg[row] = s[2][0];
        g_rneg[row] = s[3][0];
    }
}

// ---------------------------------------------------------------------------
// Single-term fp16 WMMA GEMM with cp.async double buffering.
// CTA tile 128x256, BK=32, 8 warps (2M x 4N), warp tile 64x64.
// ---------------------------------------------------------------------------
#define BM 128
#define BN 256
#define BK 32
#define LDA 40
#define LDB 264
#define A_TILE_ELEMS (BM * LDA)
#define B_TILE_ELEMS (BK * LDB)
#define STAGE_ELEMS (A_TILE_ELEMS + B_TILE_ELEMS)
#define GEMM_SMEM_BYTES (2 * STAGE_ELEMS * 2)

extern __shared__ __half g_smem_h[];

template <bool HALF_OUT>
__global__ __launch_bounds__(256, 1) void gemm_f16_1t(
    const __half* __restrict__ A, const __half* __restrict__ B, void* __restrict__ Cv,
    int K, int NN) {
    const int tid = threadIdx.x;
    const int wid = tid >> 5;
    const int lane = tid & 31;
    const int wm = wid & 1;
    const int wn = wid >> 1;

    const int n0 = blockIdx.x * BN;
    const int m0 = blockIdx.y * BM;

    const __half* Ag = A + (size_t)m0 * K;
    const __half* Bg = B + n0;

    const uint32_t smem_base = smem_u32(g_smem_h);

    const int a_row = tid >> 1;
    const int a_c0 = (tid & 1) * 2;
    const int b_row = tid >> 3;
    const int b_c = tid & 7;

    auto cp_stage = [&](int t, int p) {
        const int k0 = t * BK;
        uint32_t st = smem_base + p * STAGE_ELEMS * 2;
        uint32_t sa = st;
        uint32_t sb = st + A_TILE_ELEMS * 2;
        #pragma unroll
        for (int i = 0; i < 2; i++) {
            int c = a_c0 + i;
            cp_async16(sa + (uint32_t)(a_row * LDA + c * 8) * 2,
                       Ag + (size_t)a_row * K + k0 + c * 8);
        }
        #pragma unroll
        for (int i = 0; i < 4; i++) {
            int c = b_c + i * 8;
            cp_async16(sb + (uint32_t)(b_row * LDB + c * 8) * 2,
                       Bg + (size_t)(k0 + b_row) * NN + c * 8);
        }
    };

    wmma::fragment<wmma::accumulator, 16, 16, 16, float> acc[4][4];
    #pragma unroll
    for (int i = 0; i < 4; i++)
        #pragma unroll
        for (int j = 0; j < 4; j++) wmma::fill_fragment(acc[i][j], 0.0f);

    const int nt = K / BK;
    cp_stage(0, 0);
    CP_COMMIT();

    for (int t = 0; t < nt; t++) {
        const int p = t & 1;
        if (t + 1 < nt) {
            cp_stage(t + 1, p ^ 1);
            CP_COMMIT();
            CP_WAIT(1);
        } else {
            CP_WAIT(0);
        }
        __syncthreads();

        __half* sa = g_smem_h + p * STAGE_ELEMS;
        __half* sb = sa + A_TILE_ELEMS;

        #pragma unroll
        for (int kk = 0; kk < BK; kk += 16) {
            wmma::fragment<wmma::matrix_a, 16, 16, 16, __half, wmma::row_major> ah[4];
            #pragma unroll
            for (int i = 0; i < 4; i++)
                wmma::load_matrix_sync(ah[i], sa + (wm * 64 + i * 16) * LDA + kk, LDA);
            #pragma unroll
            for (int j = 0; j < 4; j++) {
                wmma::fragment<wmma::matrix_b, 16, 16, 16, __half, wmma::row_major> bh;
                wmma::load_matrix_sync(bh, sb + kk * LDB + wn * 64 + j * 16, LDB);
                #pragma unroll
                for (int i = 0; i < 4; i++)
                    wmma::mma_sync(acc[i][j], ah[i], bh, acc[i][j]);
            }
        }
        __syncthreads();
    }

    if (HALF_OUT) {
        __half* CgH = (__half*)Cv;
        float* scratch = reinterpret_cast<float*>(g_smem_h) + wid * 256;
        int r = lane >> 1, c8 = (lane & 1) * 8;
        #pragma unroll
        for (int i = 0; i < 4; i++) {
            #pragma unroll
            for (int j = 0; j < 4; j++) {
                wmma::store_matrix_sync(scratch, acc[i][j], 16, wmma::mem_row_major);
                __syncwarp();
                __half2 o4[4];
                #pragma unroll
                for (int q = 0; q < 4; q++)
                    o4[q] = __floats2half2_rn(scratch[r * 16 + c8 + 2 * q],
                                              scratch[r * 16 + c8 + 2 * q + 1]);
                size_t grow = (size_t)(m0 + wm * 64 + i * 16 + r);
                int gcol = n0 + wn * 64 + j * 16 + c8;
                *reinterpret_cast<uint4*>(CgH + grow * NN + gcol) =
                    *reinterpret_cast<uint4*>(o4);
                __syncwarp();
            }
        }
    } else {
        float* Cg = (float*)Cv;
        #pragma unroll
        for (int i = 0; i < 4; i++) {
            int row = m0 + wm * 64 + i * 16;
            #pragma unroll
            for (int j = 0; j < 4; j++) {
                int col = n0 + wn * 64 + j * 16;
                wmma::store_matrix_sync(Cg + (size_t)row * NN + col, acc[i][j], NN,
                                        wmma::mem_row_major);
            }
        }
    }
}

// ---------------------------------------------------------------------------
// Attention rows (per-batch chunk): row = row0 + blockIdx.x
// ---------------------------------------------------------------------------
__global__ __launch_bounds__(256) void attention_kernel(const int* __restrict__ adj,
                                                        float* __restrict__ att_out,
                                                        int row0) {
    const int row = row0 + blockIdx.x;
    const int b = row >> 11;
    const int t = threadIdx.x;
    const int lane = t & 31;
    const int wrp = t >> 5;

    const float lp = g_lpos[row];
    const float ln_ = g_lneg[row];
    const float lam = g_lam;

    const int4* arow4 = reinterpret_cast<const int4*>(adj + (size_t)row * N_);
    const float4* rp4 = reinterpret_cast<const float4*>(g_rpos + b * N_);
    const float4* rn4 = reinterpret_cast<const float4*>(g_rneg + b * N_);

    int aj[8];
    {
        int4 a0 = arow4[t * 2];
        int4 a1 = arow4[t * 2 + 1];
        aj[0] = a0.x; aj[1] = a0.y; aj[2] = a0.z; aj[3] = a0.w;
        aj[4] = a1.x; aj[5] = a1.y; aj[6] = a1.z; aj[7] = a1.w;
    }
    float rpv[8], rnv[8];
    {
        float4 r0 = rp4[t * 2], r1 = rp4[t * 2 + 1];
        rpv[0] = r0.x; rpv[1] = r0.y; rpv[2] = r0.z; rpv[3] = r0.w;
        rpv[4] = r1.x; rpv[5] = r1.y; rpv[6] = r1.z; rpv[7] = r1.w;
        float4 s0 = rn4[t * 2], s1 = rn4[t * 2 + 1];
        rnv[0] = s0.x; rnv[1] = s0.y; rnv[2] = s0.z; rnv[3] = s0.w;
        rnv[4] = s1.x; rnv[5] = s1.y; rnv[6] = s1.z; rnv[7] = s1.w;
    }

    float ep[8], en[8];
    float mp = -INFINITY, mn = -INFINITY;
    #pragma unroll
    for (int i = 0; i < 8; i++) {
        int a = aj[i];
        if (a > 0) {
            float x = lp + rpv[i] + g_relp[a];
            ep[i] = (x >= 0.f) ? x : ALPHA_ * x;
            float y = ln_ + rnv[i] + g_reln[a];
            en[i] = (y >= 0.f) ? y : ALPHA_ * y;
        } else {
            ep[i] = NEG_INF_;
            en[i] = NEG_INF_;
        }
        mp = fmaxf(mp, ep[i]);
        mn = fmaxf(mn, en[i]);
    }

    __shared__ float sm[2][8];
    #pragma unroll
    for (int o = 16; o > 0; o >>= 1) {
        mp = fmaxf(mp, __shfl_xor_sync(0xFFFFFFFFu, mp, o));
        mn = fmaxf(mn, __shfl_xor_sync(0xFFFFFFFFu, mn, o));
    }
    if (lane == 0) { sm[0][wrp] = mp; sm[1][wrp] = mn; }
    __syncthreads();
    {
        float a = sm[0][lane & 7], c = sm[1][lane & 7];
        #pragma unroll
        for (int o = 4; o > 0; o >>= 1) {
            a = fmaxf(a, __shfl_xor_sync(0xFFFFFFFFu, a, o));
            c = fmaxf(c, __shfl_xor_sync(0xFFFFFFFFu, c, o));
        }
        mp = a; mn = c;
    }

    float sp = 0.f, sn = 0.f;
    #pragma unroll
    for (int i = 0; i < 8; i++) {
        ep[i] = __expf(ep[i] - mp);
        en[i] = __expf(en[i] - mn);
        sp += ep[i];
        sn += en[i];
    }
    #pragma unroll
    for (int o = 16; o > 0; o >>= 1) {
        sp += __shfl_xor_sync(0xFFFFFFFFu, sp, o);
        sn += __shfl_xor_sync(0xFFFFFFFFu, sn, o);
    }
    __syncthreads();
    if (lane == 0) { sm[0][wrp] = sp; sm[1][wrp] = sn; }
    __syncthreads();
    {
        float a = sm[0][lane & 7], c = sm[1][lane & 7];
        #pragma unroll
        for (int o = 4; o > 0; o >>= 1) {
            a += __shfl_xor_sync(0xFFFFFFFFu, a, o);
            c += __shfl_xor_sync(0xFFFFFFFFu, c, o);
        }
        sp = a; sn = c;
    }

    const float isp = 1.0f / sp;
    const float isn = lam / sn;
    float ov[8];
    #pragma unroll
    for (int i = 0; i < 8; i++) ov[i] = ep[i] * isp - en[i] * isn;

    const size_t base = (size_t)row * N_;
    float4* orow4 = reinterpret_cast<float4*>(att_out + base);
    orow4[t * 2]     = make_float4(ov[0], ov[1], ov[2], ov[3]);
    orow4[t * 2 + 1] = make_float4(ov[4], ov[5], ov[6], ov[7]);

    __half2 hv[4];
    #pragma unroll
    for (int i = 0; i < 4; i++)
        hv[i] = __half2(__float2half_rn(ov[i * 2]), __float2half_rn(ov[i * 2 + 1]));
    reinterpret_cast<uint4*>(g_att_h16 + base)[t] = *reinterpret_cast<uint4*>(hv);
}

// ---------------------------------------------------------------------------
// LayerNorm + scale + exact GELU (per-batch chunk)
// ---------------------------------------------------------------------------
__global__ void ln_gelu_kernel(const float* __restrict__ gamma, const float* __restrict__ beta,
                               float* __restrict__ out, int row0) {
    int row = row0 + blockIdx.x;
    int t = threadIdx.x;
    const float* x = g_hprime + (size_t)row * OUT_F;
    float x0 = x[t];
    float x1 = x[t + 256];
    __shared__ float red[256];
    red[t] = x0 + x1; __syncthreads();
    for (int s = 128; s > 0; s >>= 1) { if (t < s) red[t] += red[t + s]; __syncthreads(); }
    float mu = red[0] * (1.0f / OUT_F);
    __syncthreads();
    float d0 = x0 - mu, d1 = x1 - mu;
    red[t] = d0 * d0 + d1 * d1; __syncthreads();
    for (int s = 128; s > 0; s >>= 1) { if (t < s) red[t] += red[t + s]; __syncthreads(); }
    float var = red[0] * (1.0f / OUT_F);
    float inv = rsqrtf(var + EPS_LN_);

    float y0 = (d0 * inv * gamma[t] + beta[t]) * ONE_MINUS_LAMBDA_;
    float y1 = (d1 * inv * gamma[t + 256] + beta[t + 256]) * ONE_MINUS_LAMBDA_;
    float* o = out + (size_t)row * OUT_F;
    o[t]       = y0 * 0.5f * (1.0f + erff(y0 * 0.7071067811865476f));
    o[t + 256] = y1 * 0.5f * (1.0f + erff(y1 * 0.7071067811865476f));
}

// ---------------------------------------------------------------------------
// Launch: batch-pipelined tail.
//   main: prep, hconv, attention(b) [records ev_att[b]]
//   s2:   gemm1(b) [records ev_g1[b]]
//   s3:   per b: wait(ev_att[b], ev_g1[b]) -> gemm2(b) -> ln_gelu(b)
//   main joins on ev_done at the end.
// ---------------------------------------------------------------------------
extern "C" void kernel_launch(void* const* d_in, const int* in_sizes, int n_in,
                              void* d_out, int out_size) {
    const float* h         = (const float*)d_in[0];
    const int*   adj       = (const int*)d_in[1];
    const float* W         = (const float*)d_in[2];
    const float* alp       = (const float*)d_in[3];
    const float* arp       = (const float*)d_in[4];
    const float* aln       = (const float*)d_in[5];
    const float* arn       = (const float*)d_in[6];
    const float* rel_table = (const float*)d_in[7];
    const float* a_rel_pos = (const float*)d_in[8];
    const float* a_rel_neg = (const float*)d_in[9];
    const float* ll1       = (const float*)d_in[10];
    const float* lr1       = (const float*)d_in[11];
    const float* ll2       = (const float*)d_in[12];
    const float* lr2       = (const float*)d_in[13];
    const float* gamma     = (const float*)d_in[14];
    const float* beta      = (const float*)d_in[15];
    float* out = (float*)d_out;

    const size_t GE = (size_t)B_ * N_ * OUT_F;
    const size_t AT = (size_t)B_ * N_ * N_;

    float* att_out;
    if ((size_t)out_size >= GE + AT) {
        att_out = out + GE;
    } else {
        void* p;
        cudaGetSymbolAddress(&p, g_att_fallback);
        att_out = (float*)p;
    }

    void *pHp, *p_h16, *p_W16, *p_Wh16, *p_att16;
    cudaGetSymbolAddress(&pHp, g_hprime);
    cudaGetSymbolAddress(&p_h16, g_h_h16);
    cudaGetSymbolAddress(&p_W16, g_W_h16);
    cudaGetSymbolAddress(&p_Wh16, g_Wh_h16);
    cudaGetSymbolAddress(&p_att16, g_att_h16);
    float* hprime = (float*)pHp;
    __half* h16 = (__half*)p_h16;
    __half* W16 = (__half*)p_W16;
    __half* Wh16 = (__half*)p_Wh16;
    __half* att16 = (__half*)p_att16;

    cudaFuncSetAttribute((const void*)gemm_f16_1t<true>,
                         cudaFuncAttributeMaxDynamicSharedMemorySize, GEMM_SMEM_BYTES);
    cudaFuncSetAttribute((const void*)gemm_f16_1t<false>,
                         cudaFuncAttributeMaxDynamicSharedMemorySize, GEMM_SMEM_BYTES);

    // 1) merged prep
    prep_all_kernel<<<IN_F + 1, 256>>>(W, alp, arp, aln, arn,
                                       ll1, lr1, ll2, lr2,
                                       rel_table, a_rel_pos, a_rel_neg);

    // 2) h -> fp16 + exact per-row scores
    hconv_scores_kernel<<<B_ * N_, 256>>>(h);

    // fork point: both GEMM1 chunks (s2) and attention chunks (main) depend on hconv
    cudaEventRecord(g_res.ev_fork, 0);
    cudaStreamWaitEvent(g_res.s2, g_res.ev_fork, 0);

    const size_t sH = (size_t)N_ * IN_F;      // h16 per-batch stride
    const size_t sWh = (size_t)N_ * OUT_F;    // Wh16 / hprime per-batch stride
    const size_t sAtt = (size_t)N_ * N_;      // att per-batch stride

    dim3 gridG(OUT_F / BN, N_ / BM, 1);       // 2 x 16 = 32 CTAs per batch chunk

    for (int b = 0; b < B_; b++) {
        // GEMM1 chunk b on s2: Wh16[b] = fp16( h16[b] @ W16 )
        gemm_f16_1t<true><<<gridG, 256, GEMM_SMEM_BYTES, g_res.s2>>>(
            h16 + b * sH, W16, (void*)(Wh16 + b * sWh), IN_F, OUT_F);
        cudaEventRecord(g_res.ev_g1[b], g_res.s2);

        // attention chunk b on main stream
        attention_kernel<<<N_, 256>>>(adj, att_out, b * N_);
        cudaEventRecord(g_res.ev_att[b], 0);

        // GEMM2 chunk b + ln_gelu chunk b on s3
        cudaStreamWaitEvent(g_res.s3, g_res.ev_g1[b], 0);
        cudaStreamWaitEvent(g_res.s3, g_res.ev_att[b], 0);
        gemm_f16_1t<false><<<gridG, 256, GEMM_SMEM_BYTES, g_res.s3>>>(
            att16 + b * sAtt, Wh16 + b * sWh, (void*)(hprime + b * sWh), N_, OUT_F);
        ln_gelu_kernel<<<N_, 256, 0, g_res.s3>>>(gamma, beta, out, b * N_);
    }

    // join s3 back into main stream
    cudaEventRecord(g_res.ev_done, g_res.s3);
    cudaStreamWaitEvent(0, g_res.ev_done, 0);
}

// round 16
// speedup vs baseline: 2.1104x; 2.1104x over previous
#include <cuda_runtime.h>
#include <cuda_fp16.h>
#include <mma.h>
#include <math.h>
#include <stdint.h>

using namespace nvcuda;

#define B_ 4
#define N_ 2048
#define IN_F 512
#define OUT_F 512
#define INTERNAL 256
#define REL_DIM 10
#define NUM_REL 6
#define ALPHA_ 0.2f
#define NEG_INF_ -9000000000000000.0f
#define EPS_LN_ 1e-5f

#define LAMBDA_INIT_ 0.35550906759096927f
#define ONE_MINUS_LAMBDA_ 0.64449093240903073f

// ---------------------------------------------------------------------------
// Device scratch
// ---------------------------------------------------------------------------
__device__ __align__(128) float g_hprime[(size_t)B_ * N_ * OUT_F];
__device__ __align__(128) float g_att_fallback[(size_t)B_ * N_ * N_];
__device__ __align__(128) __half g_h_h16[(size_t)B_ * N_ * IN_F];
__device__ __align__(128) __half g_W_h16[(size_t)IN_F * OUT_F];
__device__ __align__(128) __half g_Wh_h16[(size_t)B_ * N_ * OUT_F];
__device__ __align__(128) __half g_att_h16[(size_t)B_ * N_ * N_];
__device__ float g_vlp[IN_F];
__device__ float g_vrp[IN_F];
__device__ float g_vln[IN_F];
__device__ float g_vrn[IN_F];
__device__ float g_lpos[B_ * N_];
__device__ float g_rpos[B_ * N_];
__device__ float g_lneg[B_ * N_];
__device__ float g_rneg[B_ * N_];
__device__ float g_relp[NUM_REL];
__device__ float g_reln[NUM_REL];
__device__ float g_lam;

// ---------------------------------------------------------------------------
// Host-side stream/event resources
// ---------------------------------------------------------------------------
struct GraphRes {
    cudaStream_t s2 = nullptr, s3 = nullptr;
    cudaEvent_t ev_fork = nullptr, ev_g1 = nullptr;
    cudaEvent_t ev_a01 = nullptr, ev_a23 = nullptr;
    cudaEvent_t ev_s2done = nullptr, ev_s3done = nullptr;
    GraphRes() {
        cudaStreamCreateWithFlags(&s2, cudaStreamNonBlocking);
        cudaStreamCreateWithFlags(&s3, cudaStreamNonBlocking);
        cudaEventCreateWithFlags(&ev_fork, cudaEventDisableTiming);
        cudaEventCreateWithFlags(&ev_g1, cudaEventDisableTiming);
        cudaEventCreateWithFlags(&ev_a01, cudaEventDisableTiming);
        cudaEventCreateWithFlags(&ev_a23, cudaEventDisableTiming);
        cudaEventCreateWithFlags(&ev_s2done, cudaEventDisableTiming);
        cudaEventCreateWithFlags(&ev_s3done, cudaEventDisableTiming);
    }
};
static GraphRes g_res;

// ---------------------------------------------------------------------------
// cp.async helpers
// ---------------------------------------------------------------------------
__device__ __forceinline__ uint32_t smem_u32(const void* p) {
    uint32_t a;
    asm("{ .reg .u64 t; cvta.to.shared.u64 t, %1; cvt.u32.u64 %0, t; }" : "=r"(a) : "l"(p));
    return a;
}
__device__ __forceinline__ void cp_async16(uint32_t s, const void* g) {
    asm volatile("cp.async.cg.shared.global [%0], [%1], 16;" :: "r"(s), "l"(g));
}
#define CP_COMMIT() asm volatile("cp.async.commit_group;" ::: "memory")
#define CP_WAIT(n) asm volatile("cp.async.wait_group %0;" :: "n"(n) : "memory")

// ---------------------------------------------------------------------------
// Merged prep: W fold + fp16 conversion (blocks 0..IN_F-1), lambda/LUT (block IN_F)
// ---------------------------------------------------------------------------
__global__ void prep_all_kernel(const float* __restrict__ W,
                                const float* __restrict__ alp, const float* __restrict__ arp,
                                const float* __restrict__ aln, const float* __restrict__ arn,
                                const float* __restrict__ ll1, const float* __restrict__ lr1,
                                const float* __restrict__ ll2, const float* __restrict__ lr2,
                                const float* __restrict__ rel_table,
                                const float* __restrict__ a_rel_pos,
                                const float* __restrict__ a_rel_neg) {
    int t = threadIdx.x;
    if (blockIdx.x == IN_F) {
        __shared__ float s1[256];
        __shared__ float s2[256];
        s1[t] = ll1[t] * lr1[t];
        s2[t] = ll2[t] * lr2[t];
        __syncthreads();
        for (int s = 128; s > 0; s >>= 1) {
            if (t < s) { s1[t] += s1[t + s]; s2[t] += s2[t + s]; }
            __syncthreads();
        }
        if (t == 0) g_lam = expf(s1[0]) - expf(s2[0]) + LAMBDA_INIT_;
        if (t < NUM_REL) {
            float sp = 0.f, sn = 0.f;
            #pragma unroll
            for (int d = 0; d < REL_DIM; d++) {
                float r = rel_table[t * REL_DIM + d];
                sp += r * a_rel_pos[d];
                sn += r * a_rel_neg[d];
            }
            g_relp[t] = sp;
            g_reln[t] = sn;
        }
        return;
    }
    int i = blockIdx.x;
    const float* wrow = W + (size_t)i * OUT_F;
    float wp = wrow[t];
    float wn = wrow[INTERNAL + t];

    __half* wr = g_W_h16 + (size_t)i * OUT_F;
    wr[t] = __float2half_rn(wp);
    wr[INTERNAL + t] = __float2half_rn(wn);

    __shared__ float s[4][256];
    s[0][t] = wp * alp[t];
    s[1][t] = wp * arp[t];
    s[2][t] = wn * aln[t];
    s[3][t] = wn * arn[t];
    __syncthreads();
    for (int st = 128; st > 0; st >>= 1) {
        if (t < st) {
            s[0][t] += s[0][t + st];
            s[1][t] += s[1][t + st];
            s[2][t] += s[2][t + st];
            s[3][t] += s[3][t + st];
        }
        __syncthreads();
    }
    if (t == 0) {
        g_vlp[i] = s[0][0];
        g_vrp[i] = s[1][0];
        g_vln[i] = s[2][0];
        g_vrn[i] = s[3][0];
    }
}

// ---------------------------------------------------------------------------
// Fused: h -> fp16 + exact per-row scores via GEMV against folded vectors.
// ---------------------------------------------------------------------------
__global__ void hconv_scores_kernel(const float* __restrict__ h) {
    int row = blockIdx.x;
    int t = threadIdx.x;
    const float* hr = h + (size_t)row * IN_F;
    float x0 = hr[t];
    float x1 = hr[t + 256];

    __half* hh = g_h_h16 + (size_t)row * IN_F;
    hh[t] = __float2half_rn(x0);
    hh[t + 256] = __float2half_rn(x1);

    __shared__ float s[4][256];
    s[0][t] = x0 * g_vlp[t] + x1 * g_vlp[t + 256];
    s[1][t] = x0 * g_vrp[t] + x1 * g_vrp[t + 256];
    s[2][t] = x0 * g_vln[t] + x1 * g_vln[t + 256];
    s[3][t] = x0 * g_vrn[t] + x1 * g_vrn[t + 256];
    __syncthreads();
    for (int st = 128; st > 0; st >>= 1) {
        if (t < st) {
            s[0][t] += s[0][t + st];
            s[1][t] += s[1][t + st];
            s[2][t] += s[2][t + st];
            s[3][t] += s[3][t + st];
        }
        __syncthreads();
    }
    if (t == 0) {
        g_lpos[row] = s[0][0];
        g_rpos[row] = s[1][0];
        g_lneg[row] = s[2][0];
        g_rneg[row] = s[3][0];
    }
}

// ---------------------------------------------------------------------------
// Single-term fp16 WMMA GEMM with cp.async double buffering (strided batches).
// CTA tile 128x256, BK=32, 8 warps (2M x 4N), warp tile 64x64.
// ---------------------------------------------------------------------------
#define BM 128
#define BN 256
#define BK 32
#define LDA 40
#define LDB 264
#define A_TILE_ELEMS (BM * LDA)
#define B_TILE_ELEMS (BK * LDB)
#define STAGE_ELEMS (A_TILE_ELEMS + B_TILE_ELEMS)
#define GEMM_SMEM_BYTES (2 * STAGE_ELEMS * 2)

extern __shared__ __half g_smem_h[];

template <bool HALF_OUT>
__global__ __launch_bounds__(256, 1) void gemm_f16_1t(
    const __half* __restrict__ A, const __half* __restrict__ B, void* __restrict__ Cv,
    int K, int NN, size_t sA, size_t sB, size_t sC) {
    const int tid = threadIdx.x;
    const int wid = tid >> 5;
    const int lane = tid & 31;
    const int wm = wid & 1;
    const int wn = wid >> 1;

    const int n0 = blockIdx.x * BN;
    const int m0 = blockIdx.y * BM;
    const int bz = blockIdx.z;

    const __half* Ag = A + (size_t)bz * sA + (size_t)m0 * K;
    const __half* Bg = B + (size_t)bz * sB + n0;

    const uint32_t smem_base = smem_u32(g_smem_h);

    const int a_row = tid >> 1;
    const int a_c0 = (tid & 1) * 2;
    const int b_row = tid >> 3;
    const int b_c = tid & 7;

    auto cp_stage = [&](int t, int p) {
        const int k0 = t * BK;
        uint32_t st = smem_base + p * STAGE_ELEMS * 2;
        uint32_t sa = st;
        uint32_t sb = st + A_TILE_ELEMS * 2;
        #pragma unroll
        for (int i = 0; i < 2; i++) {
            int c = a_c0 + i;
            cp_async16(sa + (uint32_t)(a_row * LDA + c * 8) * 2,
                       Ag + (size_t)a_row * K + k0 + c * 8);
        }
        #pragma unroll
        for (int i = 0; i < 4; i++) {
            int c = b_c + i * 8;
            cp_async16(sb + (uint32_t)(b_row * LDB + c * 8) * 2,
                       Bg + (size_t)(k0 + b_row) * NN + c * 8);
        }
    };

    wmma::fragment<wmma::accumulator, 16, 16, 16, float> acc[4][4];
    #pragma unroll
    for (int i = 0; i < 4; i++)
        #pragma unroll
        for (int j = 0; j < 4; j++) wmma::fill_fragment(acc[i][j], 0.0f);

    const int nt = K / BK;
    cp_stage(0, 0);
    CP_COMMIT();

    for (int t = 0; t < nt; t++) {
        const int p = t & 1;
        if (t + 1 < nt) {
            cp_stage(t + 1, p ^ 1);
            CP_COMMIT();
            CP_WAIT(1);
        } else {
            CP_WAIT(0);
        }
        __syncthreads();

        __half* sa = g_smem_h + p * STAGE_ELEMS;
        __half* sb = sa + A_TILE_ELEMS;

        #pragma unroll
        for (int kk = 0; kk < BK; kk += 16) {
            wmma::fragment<wmma::matrix_a, 16, 16, 16, __half, wmma::row_major> ah[4];
            #pragma unroll
            for (int i = 0; i < 4; i++)
                wmma::load_matrix_sync(ah[i], sa + (wm * 64 + i * 16) * LDA + kk, LDA);
            #pragma unroll
            for (int j = 0; j < 4; j++) {
                wmma::fragment<wmma::matrix_b, 16, 16, 16, __half, wmma::row_major> bh;
                wmma::load_matrix_sync(bh, sb + kk * LDB + wn * 64 + j * 16, LDB);
                #pragma unroll
                for (int i = 0; i < 4; i++)
                    wmma::mma_sync(acc[i][j], ah[i], bh, acc[i][j]);
            }
        }
        __syncthreads();
    }

    if (HALF_OUT) {
        __half* CgH = (__half*)Cv + (size_t)bz * sC;
        float* scratch = reinterpret_cast<float*>(g_smem_h) + wid * 256;
        int r = lane >> 1, c8 = (lane & 1) * 8;
        #pragma unroll
        for (int i = 0; i < 4; i++) {
            #pragma unroll
            for (int j = 0; j < 4; j++) {
                wmma::store_matrix_sync(scratch, acc[i][j], 16, wmma::mem_row_major);
                __syncwarp();
                __half2 o4[4];
                #pragma unroll
                for (int q = 0; q < 4; q++)
                    o4[q] = __floats2half2_rn(scratch[r * 16 + c8 + 2 * q],
                                              scratch[r * 16 + c8 + 2 * q + 1]);
                size_t grow = (size_t)(m0 + wm * 64 + i * 16 + r);
                int gcol = n0 + wn * 64 + j * 16 + c8;
                *reinterpret_cast<uint4*>(CgH + grow * NN + gcol) =
                    *reinterpret_cast<uint4*>(o4);
                __syncwarp();
            }
        }
    } else {
        float* Cg = (float*)Cv + (size_t)bz * sC;
        #pragma unroll
        for (int i = 0; i < 4; i++) {
            int row = m0 + wm * 64 + i * 16;
            #pragma unroll
            for (int j = 0; j < 4; j++) {
                int col = n0 + wn * 64 + j * 16;
                wmma::store_matrix_sync(Cg + (size_t)row * NN + col, acc[i][j], NN,
                                        wmma::mem_row_major);
            }
        }
    }
}

// ---------------------------------------------------------------------------
// Attention rows (half-chunk): row = row0 + blockIdx.x
// ---------------------------------------------------------------------------
__global__ __launch_bounds__(256) void attention_kernel(const int* __restrict__ adj,
                                                        float* __restrict__ att_out,
                                                        int row0) {
    const int row = row0 + blockIdx.x;
    const int b = row >> 11;
    const int t = threadIdx.x;
    const int lane = t & 31;
    const int wrp = t >> 5;

    const float lp = g_lpos[row];
    const float ln_ = g_lneg[row];
    const float lam = g_lam;

    const int4* arow4 = reinterpret_cast<const int4*>(adj + (size_t)row * N_);
    const float4* rp4 = reinterpret_cast<const float4*>(g_rpos + b * N_);
    const float4* rn4 = reinterpret_cast<const float4*>(g_rneg + b * N_);

    int aj[8];
    {
        int4 a0 = arow4[t * 2];
        int4 a1 = arow4[t * 2 + 1];
        aj[0] = a0.x; aj[1] = a0.y; aj[2] = a0.z; aj[3] = a0.w;
        aj[4] = a1.x; aj[5] = a1.y; aj[6] = a1.z; aj[7] = a1.w;
    }
    float rpv[8], rnv[8];
    {
        float4 r0 = rp4[t * 2], r1 = rp4[t * 2 + 1];
        rpv[0] = r0.x; rpv[1] = r0.y; rpv[2] = r0.z; rpv[3] = r0.w;
        rpv[4] = r1.x; rpv[5] = r1.y; rpv[6] = r1.z; rpv[7] = r1.w;
        float4 s0 = rn4[t * 2], s1 = rn4[t * 2 + 1];
        rnv[0] = s0.x; rnv[1] = s0.y; rnv[2] = s0.z; rnv[3] = s0.w;
        rnv[4] = s1.x; rnv[5] = s1.y; rnv[6] = s1.z; rnv[7] = s1.w;
    }

    float ep[8], en[8];
    float mp = -INFINITY, mn = -INFINITY;
    #pragma unroll
    for (int i = 0; i < 8; i++) {
        int a = aj[i];
        if (a > 0) {
            float x = lp + rpv[i] + g_relp[a];
            ep[i] = (x >= 0.f) ? x : ALPHA_ * x;
            float y = ln_ + rnv[i] + g_reln[a];
            en[i] = (y >= 0.f) ? y : ALPHA_ * y;
        } else {
            ep[i] = NEG_INF_;
            en[i] = NEG_INF_;
        }
        mp = fmaxf(mp, ep[i]);
        mn = fmaxf(mn, en[i]);
    }

    __shared__ float sm[2][8];
    #pragma unroll
    for (int o = 16; o > 0; o >>= 1) {
        mp = fmaxf(mp, __shfl_xor_sync(0xFFFFFFFFu, mp, o));
        mn = fmaxf(mn, __shfl_xor_sync(0xFFFFFFFFu, mn, o));
    }
    if (lane == 0) { sm[0][wrp] = mp; sm[1][wrp] = mn; }
    __syncthreads();
    {
        float a = sm[0][lane & 7], c = sm[1][lane & 7];
        #pragma unroll
        for (int o = 4; o > 0; o >>= 1) {
            a = fmaxf(a, __shfl_xor_sync(0xFFFFFFFFu, a, o));
            c = fmaxf(c, __shfl_xor_sync(0xFFFFFFFFu, c, o));
        }
        mp = a; mn = c;
    }

    float sp = 0.f, sn = 0.f;
    #pragma unroll
    for (int i = 0; i < 8; i++) {
        ep[i] = __expf(ep[i] - mp);
        en[i] = __expf(en[i] - mn);
        sp += ep[i];
        sn += en[i];
    }
    #pragma unroll
    for (int o = 16; o > 0; o >>= 1) {
        sp += __shfl_xor_sync(0xFFFFFFFFu, sp, o);
        sn += __shfl_xor_sync(0xFFFFFFFFu, sn, o);
    }
    __syncthreads();
    if (lane == 0) { sm[0][wrp] = sp; sm[1][wrp] = sn; }
    __syncthreads();
    {
        float a = sm[0][lane & 7], c = sm[1][lane & 7];
        #pragma unroll
        for (int o = 4; o > 0; o >>= 1) {
            a += __shfl_xor_sync(0xFFFFFFFFu, a, o);
            c += __shfl_xor_sync(0xFFFFFFFFu, c, o);
        }
        sp = a; sn = c;
    }

    const float isp = 1.0f / sp;
    const float isn = lam / sn;
    float ov[8];
    #pragma unroll
    for (int i = 0; i < 8; i++) ov[i] = ep[i] * isp - en[i] * isn;

    const size_t base = (size_t)row * N_;
    float4* orow4 = reinterpret_cast<float4*>(att_out + base);
    orow4[t * 2]     = make_float4(ov[0], ov[1], ov[2], ov[3]);
    orow4[t * 2 + 1] = make_float4(ov[4], ov[5], ov[6], ov[7]);

    __half2 hv[4];
    #pragma unroll
    for (int i = 0; i < 4; i++)
        hv[i] = __half2(__float2half_rn(ov[i * 2]), __float2half_rn(ov[i * 2 + 1]));
    reinterpret_cast<uint4*>(g_att_h16 + base)[t] = *reinterpret_cast<uint4*>(hv);
}

// ---------------------------------------------------------------------------
// LayerNorm + scale + exact GELU (half-chunk)
// ---------------------------------------------------------------------------
__global__ void ln_gelu_kernel(const float* __restrict__ gamma, const float* __restrict__ beta,
                               float* __restrict__ out, int row0) {
    int row = row0 + blockIdx.x;
    int t = threadIdx.x;
    const float* x = g_hprime + (size_t)row * OUT_F;
    float x0 = x[t];
    float x1 = x[t + 256];
    __shared__ float red[256];
    red[t] = x0 + x1; __syncthreads();
    for (int s = 128; s > 0; s >>= 1) { if (t < s) red[t] += red[t + s]; __syncthreads(); }
    float mu = red[0] * (1.0f / OUT_F);
    __syncthreads();
    float d0 = x0 - mu, d1 = x1 - mu;
    red[t] = d0 * d0 + d1 * d1; __syncthreads();
    for (int s = 128; s > 0; s >>= 1) { if (t < s) red[t] += red[t + s]; __syncthreads(); }
    float var = red[0] * (1.0f / OUT_F);
    float inv = rsqrtf(var + EPS_LN_);

    float y0 = (d0 * inv * gamma[t] + beta[t]) * ONE_MINUS_LAMBDA_;
    float y1 = (d1 * inv * gamma[t + 256] + beta[t + 256]) * ONE_MINUS_LAMBDA_;
    float* o = out + (size_t)row * OUT_F;
    o[t]       = y0 * 0.5f * (1.0f + erff(y0 * 0.7071067811865476f));
    o[t + 256] = y1 * 0.5f * (1.0f + erff(y1 * 0.7071067811865476f));
}

// ---------------------------------------------------------------------------
// Launch: two-half pipelined tail (halves CONCURRENT on separate streams).
//   main: prep, hconv, attn(b01), attn(b23)
//   s2:   gemm1(full) -> [wait attn(b23)] gemm2(b23) -> ln_gelu(b23)
//   s3:   [wait gemm1, attn(b01)] gemm2(b01) -> ln_gelu(b01)
// ---------------------------------------------------------------------------
extern "C" void kernel_launch(void* const* d_in, const int* in_sizes, int n_in,
                              void* d_out, int out_size) {
    const float* h         = (const float*)d_in[0];
    const int*   adj       = (const int*)d_in[1];
    const float* W         = (const float*)d_in[2];
    const float* alp       = (const float*)d_in[3];
    const float* arp       = (const float*)d_in[4];
    const float* aln       = (const float*)d_in[5];
    const float* arn       = (const float*)d_in[6];
    const float* rel_table = (const float*)d_in[7];
    const float* a_rel_pos = (const float*)d_in[8];
    const float* a_rel_neg = (const float*)d_in[9];
    const float* ll1       = (const float*)d_in[10];
    const float* lr1       = (const float*)d_in[11];
    const float* ll2       = (const float*)d_in[12];
    const float* lr2       = (const float*)d_in[13];
    const float* gamma     = (const float*)d_in[14];
    const float* beta      = (const float*)d_in[15];
    float* out = (float*)d_out;

    const size_t GE = (size_t)B_ * N_ * OUT_F;
    const size_t AT = (size_t)B_ * N_ * N_;

    float* att_out;
    if ((size_t)out_size >= GE + AT) {
        att_out = out + GE;
    } else {
        void* p;
        cudaGetSymbolAddress(&p, g_att_fallback);
        att_out = (float*)p;
    }

    void *pHp, *p_h16, *p_W16, *p_Wh16, *p_att16;
    cudaGetSymbolAddress(&pHp, g_hprime);
    cudaGetSymbolAddress(&p_h16, g_h_h16);
    cudaGetSymbolAddress(&p_W16, g_W_h16);
    cudaGetSymbolAddress(&p_Wh16, g_Wh_h16);
    cudaGetSymbolAddress(&p_att16, g_att_h16);
    float* hprime = (float*)pHp;
    __half* h16 = (__half*)p_h16;
    __half* W16 = (__half*)p_W16;
    __half* Wh16 = (__half*)p_Wh16;
    __half* att16 = (__half*)p_att16;

    cudaFuncSetAttribute((const void*)gemm_f16_1t<true>,
                         cudaFuncAttributeMaxDynamicSharedMemorySize, GEMM_SMEM_BYTES);
    cudaFuncSetAttribute((const void*)gemm_f16_1t<false>,
                         cudaFuncAttributeMaxDynamicSharedMemorySize, GEMM_SMEM_BYTES);

    const size_t sWh = (size_t)N_ * OUT_F;
    const size_t sAtt = (size_t)N_ * N_;

    // 1) merged prep
    prep_all_kernel<<<IN_F + 1, 256>>>(W, alp, arp, aln, arn,
                                       ll1, lr1, ll2, lr2,
                                       rel_table, a_rel_pos, a_rel_neg);

    // 2) h -> fp16 + exact per-row scores
    hconv_scores_kernel<<<B_ * N_, 256>>>(h);

    // fork
    cudaEventRecord(g_res.ev_fork, 0);
    cudaStreamWaitEvent(g_res.s2, g_res.ev_fork, 0);

    // s2: GEMM1 full (M=8192 fold, grid 2x64)
    {
        dim3 grid(OUT_F / BN, (B_ * N_) / BM, 1);
        gemm_f16_1t<true><<<grid, 256, GEMM_SMEM_BYTES, g_res.s2>>>(
            h16, W16, (void*)Wh16, IN_F, OUT_F, 0, 0, 0);
    }
    cudaEventRecord(g_res.ev_g1, g_res.s2);

    // main: attention halves
    attention_kernel<<<2 * N_, 256>>>(adj, att_out, 0);
    cudaEventRecord(g_res.ev_a01, 0);
    attention_kernel<<<2 * N_, 256>>>(adj, att_out, 2 * N_);
    cudaEventRecord(g_res.ev_a23, 0);

    dim3 gridH(OUT_F / BN, N_ / BM, 2);   // 2x16x2 = 64 CTAs per half

    // s3: gemm2 half b01 + ln_gelu b01 (concurrent with attn(b23) and s2's half)
    cudaStreamWaitEvent(g_res.s3, g_res.ev_g1, 0);
    cudaStreamWaitEvent(g_res.s3, g_res.ev_a01, 0);
    gemm_f16_1t<false><<<gridH, 256, GEMM_SMEM_BYTES, g_res.s3>>>(
        att16, Wh16, (void*)hprime, N_, OUT_F, sAtt, sWh, sWh);
    ln_gelu_kernel<<<2 * N_, 256, 0, g_res.s3>>>(gamma, beta, out, 0);
    cudaEventRecord(g_res.ev_s3done, g_res.s3);

    // s2: gemm2 half b23 + ln_gelu b23 (after gemm1 on same stream + attn(b23))
    cudaStreamWaitEvent(g_res.s2, g_res.ev_a23, 0);
    gemm_f16_1t<false><<<gridH, 256, GEMM_SMEM_BYTES, g_res.s2>>>(
        att16 + 2 * sAtt, Wh16 + 2 * sWh, (void*)(hprime + 2 * sWh), N_, OUT_F,
        sAtt, sWh, sWh);
    ln_gelu_kernel<<<2 * N_, 256, 0, g_res.s2>>>(gamma, beta, out, 2 * N_);
    cudaEventRecord(g_res.ev_s2done, g_res.s2);

    // join both side streams back into main
    cudaStreamWaitEvent(0, g_res.ev_s3done, 0);
    cudaStreamWaitEvent(0, g_res.ev_s2done, 0);
}